// round 4
// baseline (speedup 1.0000x reference)
#include <cuda_runtime.h>
#include <cuda_bf16.h>

// Accumulators in device globals (no allocations allowed). Zero at module
// load; the last finishing block resets them each invocation, so the kernel
// is deterministic across graph replays.
__device__ double g_pos_sum;
__device__ double g_neg_sum;
__device__ unsigned long long g_num_pos;
__device__ unsigned int g_ticket;

__device__ __forceinline__ void row_scalar(
    float dot, float n1, float n2, long long t,
    float& lpos, float& lneg, unsigned int& lnp)
{
    float denom = fmaxf(sqrtf(n1) * sqrtf(n2), 1e-6f);
    float d = dot / denom;
    if (t == 1) {
        // (2/BETA) * softplus(-BETA*(d-0.5)), BETA=0.5 -> 4*softplus(x)
        float x = -0.5f * (d - 0.5f);
        float sp = fmaxf(x, 0.0f) + log1pf(expf(-fabsf(x)));
        lpos += 4.0f * sp;
        lnp  += 1u;
    } else {
        // (2/ALPHA) * softplus(ALPHA*(d-2)), ALPHA=50 -> 0.04*softplus(x)
        float x = 50.0f * (d - 2.0f);
        float sp = fmaxf(x, 0.0f) + log1pf(expf(-fabsf(x)));
        lneg += 0.04f * sp;
    }
}

__global__ void __launch_bounds__(256) bl_fused_kernel(
    const float* __restrict__ o1,
    const float* __restrict__ o2,
    const long long* __restrict__ tgt,
    float* __restrict__ out,
    int N)
{
    const int lane    = threadIdx.x & 31;
    const int gwarp   = (blockIdx.x * blockDim.x + threadIdx.x) >> 5;
    const int nwarps  = (gridDim.x * blockDim.x) >> 5;

    // Contiguous balanced chunk per warp: sequential streaming -> page/TLB
    // and DRAM row-buffer locality. First `rem` warps take one extra row.
    const int base  = N / nwarps;
    const int rem   = N % nwarps;
    const int extra = (gwarp < rem) ? 1 : 0;
    const int start = gwarp * base + (gwarp < rem ? gwarp : rem);
    const int end   = start + base + extra;

    float lpos = 0.0f;
    float lneg = 0.0f;
    unsigned int lnp = 0;

    int r = start;
    // Main loop: two adjacent rows per iteration. 16 front-batched LDG.128
    // over 4KB contiguous per input array -> 2x per-warp MLP.
    for (; r + 1 < end; r += 2) {
        const float4* __restrict__ a0 = (const float4*)(o1 + (size_t)r * 512);
        const float4* __restrict__ b0 = (const float4*)(o2 + (size_t)r * 512);
        const float4* __restrict__ a1 = a0 + 128;
        const float4* __restrict__ b1 = b0 + 128;

        float4 xa[4], ya[4], xb[4], yb[4];
        #pragma unroll
        for (int i = 0; i < 4; i++) { xa[i] = __ldcs(&a0[lane + 32 * i]); }
        #pragma unroll
        for (int i = 0; i < 4; i++) { ya[i] = __ldcs(&b0[lane + 32 * i]); }
        #pragma unroll
        for (int i = 0; i < 4; i++) { xb[i] = __ldcs(&a1[lane + 32 * i]); }
        #pragma unroll
        for (int i = 0; i < 4; i++) { yb[i] = __ldcs(&b1[lane + 32 * i]); }

        float dot0 = 0.0f, n10 = 0.0f, n20 = 0.0f;
        float dot1 = 0.0f, n11 = 0.0f, n21 = 0.0f;
        #pragma unroll
        for (int i = 0; i < 4; i++) {
            float4 x = xa[i], y = ya[i];
            dot0 = fmaf(x.x, y.x, dot0); dot0 = fmaf(x.y, y.y, dot0);
            dot0 = fmaf(x.z, y.z, dot0); dot0 = fmaf(x.w, y.w, dot0);
            n10  = fmaf(x.x, x.x, n10);  n10  = fmaf(x.y, x.y, n10);
            n10  = fmaf(x.z, x.z, n10);  n10  = fmaf(x.w, x.w, n10);
            n20  = fmaf(y.x, y.x, n20);  n20  = fmaf(y.y, y.y, n20);
            n20  = fmaf(y.z, y.z, n20);  n20  = fmaf(y.w, y.w, n20);
        }
        #pragma unroll
        for (int i = 0; i < 4; i++) {
            float4 x = xb[i], y = yb[i];
            dot1 = fmaf(x.x, y.x, dot1); dot1 = fmaf(x.y, y.y, dot1);
            dot1 = fmaf(x.z, y.z, dot1); dot1 = fmaf(x.w, y.w, dot1);
            n11  = fmaf(x.x, x.x, n11);  n11  = fmaf(x.y, x.y, n11);
            n11  = fmaf(x.z, x.z, n11);  n11  = fmaf(x.w, x.w, n11);
            n21  = fmaf(y.x, y.x, n21);  n21  = fmaf(y.y, y.y, n21);
            n21  = fmaf(y.z, y.z, n21);  n21  = fmaf(y.w, y.w, n21);
        }

        // Warp reduction of six partials.
        #pragma unroll
        for (int off = 16; off > 0; off >>= 1) {
            dot0 += __shfl_xor_sync(0xffffffffu, dot0, off);
            n10  += __shfl_xor_sync(0xffffffffu, n10,  off);
            n20  += __shfl_xor_sync(0xffffffffu, n20,  off);
            dot1 += __shfl_xor_sync(0xffffffffu, dot1, off);
            n11  += __shfl_xor_sync(0xffffffffu, n11,  off);
            n21  += __shfl_xor_sync(0xffffffffu, n21,  off);
        }

        if (lane == 0) {
            long long t0 = tgt[r];
            long long t1 = tgt[r + 1];
            row_scalar(dot0, n10, n20, t0, lpos, lneg, lnp);
            row_scalar(dot1, n11, n21, t1, lpos, lneg, lnp);
        }
    }

    // Cleanup: odd trailing row.
    if (r < end) {
        const float4* __restrict__ a = (const float4*)(o1 + (size_t)r * 512);
        const float4* __restrict__ b = (const float4*)(o2 + (size_t)r * 512);
        float dot = 0.0f, n1 = 0.0f, n2 = 0.0f;
        #pragma unroll
        for (int i = 0; i < 4; i++) {
            float4 x = __ldcs(&a[lane + 32 * i]);
            float4 y = __ldcs(&b[lane + 32 * i]);
            dot = fmaf(x.x, y.x, dot); dot = fmaf(x.y, y.y, dot);
            dot = fmaf(x.z, y.z, dot); dot = fmaf(x.w, y.w, dot);
            n1  = fmaf(x.x, x.x, n1);  n1  = fmaf(x.y, x.y, n1);
            n1  = fmaf(x.z, x.z, n1);  n1  = fmaf(x.w, x.w, n1);
            n2  = fmaf(y.x, y.x, n2);  n2  = fmaf(y.y, y.y, n2);
            n2  = fmaf(y.z, y.z, n2);  n2  = fmaf(y.w, y.w, n2);
        }
        #pragma unroll
        for (int off = 16; off > 0; off >>= 1) {
            dot += __shfl_xor_sync(0xffffffffu, dot, off);
            n1  += __shfl_xor_sync(0xffffffffu, n1,  off);
            n2  += __shfl_xor_sync(0xffffffffu, n2,  off);
        }
        if (lane == 0) {
            row_scalar(dot, n1, n2, tgt[r], lpos, lneg, lnp);
        }
    }

    // Block reduction of per-warp (lane 0) partials.
    __shared__ float s_pos[8];
    __shared__ float s_neg[8];
    __shared__ unsigned int s_np[8];
    const int wid = threadIdx.x >> 5;
    if (lane == 0) {
        s_pos[wid] = lpos;
        s_neg[wid] = lneg;
        s_np[wid]  = lnp;
    }
    __syncthreads();

    if (threadIdx.x == 0) {
        float bp = 0.0f, bn = 0.0f;
        unsigned int np = 0;
        const int nw = blockDim.x >> 5;
        for (int i = 0; i < nw; i++) {
            bp += s_pos[i];
            bn += s_neg[i];
            np += s_np[i];
        }
        atomicAdd(&g_pos_sum, (double)bp);
        atomicAdd(&g_neg_sum, (double)bn);
        atomicAdd(&g_num_pos, (unsigned long long)np);

        // Make partials visible before taking a ticket.
        __threadfence();
        unsigned int ticket = atomicAdd(&g_ticket, 1u);

        if (ticket == gridDim.x - 1) {
            // Last block: finalize and reset for the next graph replay.
            double ps = g_pos_sum;
            double ns = g_neg_sum;
            double npos = (double)g_num_pos;
            double nneg = (double)N - npos;
            double pl = ps / (npos > 1.0 ? npos : 1.0);
            double nl = ns / (nneg > 1.0 ? nneg : 1.0);
            out[0] = (float)(pl + nl);

            g_pos_sum = 0.0;
            g_neg_sum = 0.0;
            g_num_pos = 0ull;
            g_ticket  = 0u;
        }
    }
}

extern "C" void kernel_launch(void* const* d_in, const int* in_sizes, int n_in,
                              void* d_out, int out_size) {
    const float*     o1  = (const float*)d_in[0];
    const float*     o2  = (const float*)d_in[1];
    const long long* tgt = (const long long*)d_in[2];
    float* out = (float*)d_out;

    const int N = in_sizes[2];  // target has one element per row

    // Launch exactly ONE resident wave: blocks/SM from the occupancy
    // calculator (accounts for actual reg usage) x SM count. Pure host
    // queries — graph-capture safe, no allocations, deterministic.
    int dev = 0;
    cudaGetDevice(&dev);
    int num_sms = 148;
    cudaDeviceGetAttribute(&num_sms, cudaDevAttrMultiProcessorCount, dev);
    int blocks_per_sm = 6;
    cudaOccupancyMaxActiveBlocksPerMultiprocessor(&blocks_per_sm,
                                                  bl_fused_kernel, 256, 0);
    if (blocks_per_sm < 1) blocks_per_sm = 1;
    int grid = num_sms * blocks_per_sm;

    bl_fused_kernel<<<grid, 256>>>(o1, o2, tgt, out, N);
}

// round 5
// speedup vs baseline: 1.0595x; 1.0595x over previous
#include <cuda_runtime.h>
#include <cuda_bf16.h>

// Accumulators in device globals (no allocations allowed). Zero at module
// load; the last finishing block resets them each invocation, so the kernel
// is deterministic across graph replays.
__device__ double g_pos_sum;
__device__ double g_neg_sum;
__device__ unsigned long long g_num_pos;
__device__ unsigned int g_ticket;

__global__ void __launch_bounds__(256, 7) bl_fused_kernel(
    const float* __restrict__ o1,
    const float* __restrict__ o2,
    const long long* __restrict__ tgt,
    float* __restrict__ out,
    int N)
{
    const int lane    = threadIdx.x & 31;
    const int gwarp   = (blockIdx.x * blockDim.x + threadIdx.x) >> 5;
    const int nwarps  = (gridDim.x * blockDim.x) >> 5;

    float lpos = 0.0f;
    float lneg = 0.0f;
    unsigned int lnp = 0;

    for (int r = gwarp; r < N; r += nwarps) {
        // Prefetch target early so its latency overlaps the FMA+shuffle phase.
        long long t = (lane == 0) ? tgt[r] : 0;

        const float4* __restrict__ a = (const float4*)(o1 + (size_t)r * 512);
        const float4* __restrict__ b = (const float4*)(o2 + (size_t)r * 512);

        float dot = 0.0f, n1 = 0.0f, n2 = 0.0f;
        #pragma unroll
        for (int i = 0; i < 4; i++) {
            float4 x = __ldcs(&a[lane + 32 * i]);
            float4 y = __ldcs(&b[lane + 32 * i]);
            dot = fmaf(x.x, y.x, dot); dot = fmaf(x.y, y.y, dot);
            dot = fmaf(x.z, y.z, dot); dot = fmaf(x.w, y.w, dot);
            n1  = fmaf(x.x, x.x, n1);  n1  = fmaf(x.y, x.y, n1);
            n1  = fmaf(x.z, x.z, n1);  n1  = fmaf(x.w, x.w, n1);
            n2  = fmaf(y.x, y.x, n2);  n2  = fmaf(y.y, y.y, n2);
            n2  = fmaf(y.z, y.z, n2);  n2  = fmaf(y.w, y.w, n2);
        }

        // Warp reduction of the three partials.
        #pragma unroll
        for (int off = 16; off > 0; off >>= 1) {
            dot += __shfl_xor_sync(0xffffffffu, dot, off);
            n1  += __shfl_xor_sync(0xffffffffu, n1,  off);
            n2  += __shfl_xor_sync(0xffffffffu, n2,  off);
        }

        if (lane == 0) {
            float denom = fmaxf(sqrtf(n1) * sqrtf(n2), 1e-6f);
            float d = dot / denom;

            // Branchless: compute both terms, select on target.
            // pos: (2/BETA)*softplus(-BETA*(d-0.5)), BETA=0.5 -> 4*softplus(xp)
            float xp  = -0.5f * (d - 0.5f);
            float spp = fmaxf(xp, 0.0f) + log1pf(expf(-fabsf(xp)));
            // neg: (2/ALPHA)*softplus(ALPHA*(d-2)), ALPHA=50 -> 0.04*softplus(xn)
            float xn  = 50.0f * (d - 2.0f);
            float spn = fmaxf(xn, 0.0f) + log1pf(expf(-fabsf(xn)));

            bool ispos = (t == 1);
            lpos += ispos ? 4.0f * spp : 0.0f;
            lneg += ispos ? 0.0f : 0.04f * spn;
            lnp  += ispos ? 1u : 0u;
        }
    }

    // Block reduction of per-warp (lane 0) partials.
    __shared__ float s_pos[8];
    __shared__ float s_neg[8];
    __shared__ unsigned int s_np[8];
    const int wid = threadIdx.x >> 5;
    if (lane == 0) {
        s_pos[wid] = lpos;
        s_neg[wid] = lneg;
        s_np[wid]  = lnp;
    }
    __syncthreads();

    if (threadIdx.x == 0) {
        float bp = 0.0f, bn = 0.0f;
        unsigned int np = 0;
        const int nw = blockDim.x >> 5;
        for (int i = 0; i < nw; i++) {
            bp += s_pos[i];
            bn += s_neg[i];
            np += s_np[i];
        }
        atomicAdd(&g_pos_sum, (double)bp);
        atomicAdd(&g_neg_sum, (double)bn);
        atomicAdd(&g_num_pos, (unsigned long long)np);

        // Make partials visible before taking a ticket.
        __threadfence();
        unsigned int ticket = atomicAdd(&g_ticket, 1u);

        if (ticket == gridDim.x - 1) {
            // Last block: finalize and reset for the next graph replay.
            double ps = g_pos_sum;
            double ns = g_neg_sum;
            double npos = (double)g_num_pos;
            double nneg = (double)N - npos;
            double pl = ps / (npos > 1.0 ? npos : 1.0);
            double nl = ns / (nneg > 1.0 ? nneg : 1.0);
            out[0] = (float)(pl + nl);

            g_pos_sum = 0.0;
            g_neg_sum = 0.0;
            g_num_pos = 0ull;
            g_ticket  = 0u;
        }
    }
}

extern "C" void kernel_launch(void* const* d_in, const int* in_sizes, int n_in,
                              void* d_out, int out_size) {
    const float*     o1  = (const float*)d_in[0];
    const float*     o2  = (const float*)d_in[1];
    const long long* tgt = (const long long*)d_in[2];
    float* out = (float*)d_out;

    const int N = in_sizes[2];  // target has one element per row

    // Launch exactly ONE resident wave: blocks/SM from the occupancy
    // calculator (accounts for actual reg usage) x SM count. Pure host
    // queries — graph-capture safe, no allocations, deterministic.
    int dev = 0;
    cudaGetDevice(&dev);
    int num_sms = 148;
    cudaDeviceGetAttribute(&num_sms, cudaDevAttrMultiProcessorCount, dev);
    int blocks_per_sm = 7;
    cudaOccupancyMaxActiveBlocksPerMultiprocessor(&blocks_per_sm,
                                                  bl_fused_kernel, 256, 0);
    if (blocks_per_sm < 1) blocks_per_sm = 1;
    int grid = num_sms * blocks_per_sm;

    bl_fused_kernel<<<grid, 256>>>(o1, o2, tgt, out, N);
}